// round 8
// baseline (speedup 1.0000x reference)
#include <cuda_runtime.h>
#include <cuda_bf16.h>
#include <cstdint>

// Shapes (fixed by the problem)
#define B 4
#define C 256
#define NHEADS 8
#define DK 32
#define TN 2304            // H*W
#define BH (B * NHEADS)
#define NBLK (TN / 8)      // 288 8-row token blocks
#define SCALE 0.17677669529663687f  // 1/sqrt(32)
#define LOG2E 1.4426950408889634f

// Fragment-ordered bf16 scratch (u32 words):
__device__ uint32_t g_qt[BH * NBLK * 2 * 64];
__device__ uint32_t g_kt[BH * NBLK * 2 * 64];
__device__ uint32_t g_v [BH * 4 * 144 * 64];
__device__ uint32_t g_xf[B * NBLK * 16 * 64];
__device__ uint32_t g_wf[3 * 32 * 16 * 64];

// ---------------------------------------------------------------------------
__device__ __forceinline__ float ex2(float x) {
    float y;
    asm("ex2.approx.f32 %0, %1;" : "=f"(y) : "f"(x));
    return y;
}

// deg-4 poly exp2 on the fma pipe (immediate-operand FFMAs, rt~1).
__device__ __forceinline__ float exp2poly(float t) {
    float z = t + 12582912.0f;                    // 1.5*2^23 rounding trick
    int n = __float_as_int(z) - __float_as_int(12582912.0f);
    float f = t - (z - 12582912.0f);              // f in [-0.5, 0.5]
    float p =        9.6181291076e-3f;
    p = fmaf(p, f,   5.5504108665e-2f);
    p = fmaf(p, f,   2.4022650696e-1f);
    p = fmaf(p, f,   6.9314718056e-1f);
    p = fmaf(p, f,   1.0f);
    return __int_as_float(__float_as_int(p) + (n << 23));
}

__device__ __forceinline__ uint32_t pack_bf16(float lo, float hi) {
    uint32_t r;
    asm("cvt.rn.bf16x2.f32 %0, %1, %2;" : "=r"(r) : "f"(hi), "f"(lo));
    return r;
}

__device__ __forceinline__ void mma_bf16(float c[4],
                                         uint32_t a0, uint32_t a1, uint32_t a2, uint32_t a3,
                                         uint32_t b0, uint32_t b1) {
    asm volatile(
        "mma.sync.aligned.m16n8k16.row.col.f32.bf16.bf16.f32 "
        "{%0,%1,%2,%3}, {%4,%5,%6,%7}, {%8,%9}, {%0,%1,%2,%3};"
        : "+f"(c[0]), "+f"(c[1]), "+f"(c[2]), "+f"(c[3])
        : "r"(a0), "r"(a1), "r"(a2), "r"(a3), "r"(b0), "r"(b1));
}

// ---------------------------------------------------------------------------
// prep_w: W[o][c] fp32 -> g_wf frag blocks (bf16). wq scaled by SCALE*LOG2E.
// ---------------------------------------------------------------------------
__global__ __launch_bounds__(256) void prep_w_kernel(
    const float* __restrict__ wq,
    const float* __restrict__ wk,
    const float* __restrict__ wv,
    uint32_t* __restrict__ wf)
{
    int t = blockIdx.x * 256 + threadIdx.x;      // 0 .. 49151
    int proj = t >> 14;
    int r = t & 16383;
    int lane = r & 31;
    int kc = (r >> 5) & 15;
    int blk = r >> 9;
    int o  = blk * 8 + (lane >> 2);
    int tg = lane & 3;
    int c0 = kc * 16 + tg * 2;

    const float* w = (proj == 0) ? wq : (proj == 1) ? wk : wv;
    float s = (proj == 0) ? (SCALE * LOG2E) : 1.0f;

    float2 lo = *(const float2*)(w + o * C + c0);
    float2 hi = *(const float2*)(w + o * C + c0 + 8);
    uint2 out;
    out.x = pack_bf16(lo.x * s, lo.y * s);
    out.y = pack_bf16(hi.x * s, hi.y * s);
    *(uint2*)(wf + ((size_t)(proj * 32 + blk) * 16 + kc) * 64 + lane * 2) = out;
}

// ---------------------------------------------------------------------------
// prep_x: x[b][c][n] fp32 -> g_xf frag blocks (rows = tokens, k = c).
// ---------------------------------------------------------------------------
__global__ __launch_bounds__(256) void prep_x_kernel(
    const float* __restrict__ x,
    uint32_t* __restrict__ xf)
{
    int b = blockIdx.z;
    int t = blockIdx.x * 256 + threadIdx.x;
    int lane = t & 31;
    int kc = (t >> 5) & 15;
    int blk = t >> 9;
    int n  = blk * 8 + (lane >> 2);
    int tg = lane & 3;
    int c0 = kc * 16 + tg * 2;

    const float* xb = x + (size_t)b * C * TN;
    float a0 = xb[(size_t)(c0    ) * TN + n];
    float a1 = xb[(size_t)(c0 + 1) * TN + n];
    float a2 = xb[(size_t)(c0 + 8) * TN + n];
    float a3 = xb[(size_t)(c0 + 9) * TN + n];
    uint2 out;
    out.x = pack_bf16(a0, a1);
    out.y = pack_bf16(a2, a3);
    *(uint2*)(xf + ((size_t)(b * NBLK + blk) * 16 + kc) * 64 + lane * 2) = out;
}

// ---------------------------------------------------------------------------
// Fused projection GEMM, bf16 HMMA, zero smem. grid (18, 12, B).
// ---------------------------------------------------------------------------
__global__ __launch_bounds__(128) void proj_kernel(
    const uint32_t* __restrict__ xf,
    const uint32_t* __restrict__ wf,
    uint32_t* __restrict__ qt,
    uint32_t* __restrict__ kt,
    uint32_t* __restrict__ vt)
{
    const int tid  = threadIdx.x;
    const int warp = tid >> 5;
    const int lane = tid & 31;
    const int gid  = lane >> 2;
    const int tig  = lane & 3;

    const int b    = blockIdx.z;
    const int proj = blockIdx.y >> 2;
    const int ob   = (blockIdx.y & 3) * 64;
    const int rw   = blockIdx.x * 128 + warp * 32;

    const uint32_t* xb = xf + ((size_t)(b * NBLK + (rw >> 3)) * 16) * 64;
    const uint32_t* wb = wf + ((size_t)(proj * 32 + (ob >> 3)) * 16) * 64;

    float acc[2][8][4];
#pragma unroll
    for (int mt = 0; mt < 2; mt++)
#pragma unroll
        for (int nt = 0; nt < 8; nt++)
#pragma unroll
            for (int r = 0; r < 4; r++) acc[mt][nt][r] = 0.f;

#pragma unroll
    for (int kc = 0; kc < 16; kc++) {
        uint32_t a[2][4];
#pragma unroll
        for (int mt = 0; mt < 2; mt++) {
            const uint32_t* p = xb + ((size_t)(mt * 2) * 16 + kc) * 64 + lane * 2;
            uint2 w0 = *(const uint2*)p;
            uint2 w1 = *(const uint2*)(p + 16 * 64);
            a[mt][0] = w0.x; a[mt][1] = w1.x; a[mt][2] = w0.y; a[mt][3] = w1.y;
        }
#pragma unroll
        for (int nt = 0; nt < 8; nt++) {
            uint2 bv = *(const uint2*)(wb + ((size_t)nt * 16 + kc) * 64 + lane * 2);
#pragma unroll
            for (int mt = 0; mt < 2; mt++)
                mma_bf16(acc[mt][nt], a[mt][0], a[mt][1], a[mt][2], a[mt][3],
                         bv.x, bv.y);
        }
    }

    if (proj < 2) {
        uint32_t* dst = (proj == 0) ? qt : kt;
#pragma unroll
        for (int ntp = 0; ntp < 4; ntp++) {
            int nt0 = 2 * ntp;
            int o   = ob + nt0 * 8 + 2 * tig;
            int h   = o >> 5;
            int bh  = b * NHEADS + h;
            int kcq = (o >> 4) & 1;
            size_t cbase = (size_t)bh * (NBLK * 128) + (size_t)kcq * 64
                         + (gid * 4 + tig) * 2;
#pragma unroll
            for (int mt = 0; mt < 2; mt++) {
                int n = rw + mt * 16 + gid;
                size_t addr = cbase + (size_t)(n >> 3) * 128;
                uint2 wlo, whi;
                wlo.x = pack_bf16(acc[mt][nt0    ][0], acc[mt][nt0    ][1]);
                wlo.y = pack_bf16(acc[mt][nt0 + 1][0], acc[mt][nt0 + 1][1]);
                whi.x = pack_bf16(acc[mt][nt0    ][2], acc[mt][nt0    ][3]);
                whi.y = pack_bf16(acc[mt][nt0 + 1][2], acc[mt][nt0 + 1][3]);
                *(uint2*)(dst + addr)       = wlo;
                *(uint2*)(dst + addr + 128) = whi;
            }
        }
    } else {
        bool even = (gid & 1) == 0;
#pragma unroll
        for (int nt = 0; nt < 8; nt++) {
            int o = ob + nt * 8 + 2 * tig + (even ? 0 : 1);
            int d8 = (o & 31) >> 3;
            int bh = b * NHEADS + (o >> 5);
            size_t base = ((size_t)bh * 4 + d8) * (144 * 64);
#pragma unroll
            for (int mt = 0; mt < 2; mt++) {
                float c0 = acc[mt][nt][0], c1 = acc[mt][nt][1];
                float c2 = acc[mt][nt][2], c3 = acc[mt][nt][3];
                float t0 = __shfl_xor_sync(0xffffffffu, c0, 4);
                float t1 = __shfl_xor_sync(0xffffffffu, c1, 4);
                float t2 = __shfl_xor_sync(0xffffffffu, c2, 4);
                float t3 = __shfl_xor_sync(0xffffffffu, c3, 4);
                int n   = rw + mt * 16 + gid;
                int key = n - (gid & 1);
                uint2 wv;
                if (even) { wv.x = pack_bf16(c0, t0); wv.y = pack_bf16(c2, t2); }
                else      { wv.x = pack_bf16(t1, c1); wv.y = pack_bf16(t3, c3); }
                size_t addr = base + (size_t)(key >> 4) * 64
                            + ((o & 7) * 4 + ((key >> 1) & 3)) * 2;
                *(uint2*)(vt + addr) = wv;
            }
        }
    }
}

// ---------------------------------------------------------------------------
// Flash attention: bf16 HMMA; exp split across MUFU + fma pipes; tile
// processed in two 16-key halves to shorten dep chains and cut live regs.
// ---------------------------------------------------------------------------
__global__ __launch_bounds__(128, 4) void attn_kernel(
    const uint32_t* __restrict__ qt,
    const uint32_t* __restrict__ kt,
    const uint32_t* __restrict__ v,
    const float* __restrict__ x,
    float* __restrict__ out)
{
    const int tid  = threadIdx.x;
    const int warp = tid >> 5;
    const int lane = tid & 31;
    const int gid  = lane >> 2;
    const int tig  = lane & 3;

    const int n0 = blockIdx.x * 128;
    const int bh = blockIdx.z * NHEADS + blockIdx.y;
    const uint32_t* qtb = qt + (size_t)bh * NBLK * 128;
    const uint32_t* ktb = kt + (size_t)bh * NBLK * 128;
    const uint32_t* vb  = v  + (size_t)bh * 4 * 144 * 64;

    uint32_t qa[2][2][4];
    {
        int jq = (n0 >> 3) + warp * 4;
#pragma unroll
        for (int mt = 0; mt < 2; mt++)
#pragma unroll
            for (int kc = 0; kc < 2; kc++) {
                const uint32_t* p = qtb + (size_t)(jq + mt * 2) * 128 + kc * 64 + lane * 2;
                uint2 w0 = *(const uint2*)p;
                uint2 w1 = *(const uint2*)(p + 128);
                qa[mt][kc][0] = w0.x;
                qa[mt][kc][1] = w1.x;
                qa[mt][kc][2] = w0.y;
                qa[mt][kc][3] = w1.y;
            }
    }

    float o[2][4][4];
    float lacc[2][2];
#pragma unroll
    for (int mt = 0; mt < 2; mt++) {
        lacc[mt][0] = 0.f; lacc[mt][1] = 0.f;
#pragma unroll
        for (int nt = 0; nt < 4; nt++)
#pragma unroll
            for (int r = 0; r < 4; r++) o[mt][nt][r] = 0.f;
    }

    for (int j0 = 0; j0 < TN; j0 += 32) {
        uint32_t kf[4][2][2], vf[4][2][2];
        {
            const uint32_t* kp = ktb + (size_t)(j0 >> 3) * 128 + lane * 2;
#pragma unroll
            for (int nt = 0; nt < 4; nt++)
#pragma unroll
                for (int kc = 0; kc < 2; kc++) {
                    uint2 wv = *(const uint2*)(kp + nt * 128 + kc * 64);
                    kf[nt][kc][0] = wv.x; kf[nt][kc][1] = wv.y;
                }
            const uint32_t* vp = vb + (size_t)(j0 >> 4) * 64 + lane * 2;
#pragma unroll
            for (int nt = 0; nt < 4; nt++)
#pragma unroll
                for (int kc = 0; kc < 2; kc++) {
                    uint2 wv = *(const uint2*)(vp + (size_t)nt * 144 * 64 + kc * 64);
                    vf[nt][kc][0] = wv.x; vf[nt][kc][1] = wv.y;
                }
        }

        // two 16-key halves: S -> exp -> pack -> PV per half
#pragma unroll
        for (int p = 0; p < 2; p++) {
            float sc[2][2][4];
#pragma unroll
            for (int mt = 0; mt < 2; mt++)
#pragma unroll
                for (int nl = 0; nl < 2; nl++)
#pragma unroll
                    for (int r = 0; r < 4; r++) sc[mt][nl][r] = 0.f;

#pragma unroll
            for (int kc = 0; kc < 2; kc++)
#pragma unroll
                for (int nl = 0; nl < 2; nl++)
#pragma unroll
                    for (int mt = 0; mt < 2; mt++)
                        mma_bf16(sc[mt][nl], qa[mt][kc][0], qa[mt][kc][1],
                                 qa[mt][kc][2], qa[mt][kc][3],
                                 kf[2 * p + nl][kc][0], kf[2 * p + nl][kc][1]);

            // exp: rows h=0 on MUFU, rows h=1 on fma-pipe poly (pipe balance)
#pragma unroll
            for (int mt = 0; mt < 2; mt++)
#pragma unroll
                for (int nl = 0; nl < 2; nl++) {
                    float p0 = ex2(sc[mt][nl][0]);
                    float p1 = ex2(sc[mt][nl][1]);
                    float p2 = exp2poly(sc[mt][nl][2]);
                    float p3 = exp2poly(sc[mt][nl][3]);
                    sc[mt][nl][0] = p0; sc[mt][nl][1] = p1;
                    sc[mt][nl][2] = p2; sc[mt][nl][3] = p3;
                    lacc[mt][0] += p0 + p1;
                    lacc[mt][1] += p2 + p3;
                }

#pragma unroll
            for (int mt = 0; mt < 2; mt++) {
                uint32_t a0 = pack_bf16(sc[mt][0][0], sc[mt][0][1]);
                uint32_t a1 = pack_bf16(sc[mt][0][2], sc[mt][0][3]);
                uint32_t a2 = pack_bf16(sc[mt][1][0], sc[mt][1][1]);
                uint32_t a3 = pack_bf16(sc[mt][1][2], sc[mt][1][3]);
#pragma unroll
                for (int nt = 0; nt < 4; nt++)
                    mma_bf16(o[mt][nt], a0, a1, a2, a3,
                             vf[nt][p][0], vf[nt][p][1]);
            }
        }
    }

    float inv[2][2];
#pragma unroll
    for (int mt = 0; mt < 2; mt++)
#pragma unroll
        for (int h = 0; h < 2; h++) {
            float l = lacc[mt][h];
            l += __shfl_xor_sync(0xffffffffu, l, 1);
            l += __shfl_xor_sync(0xffffffffu, l, 2);
            inv[mt][h] = 1.f / l;
        }

    __shared__ float psf[128 * 36];
#pragma unroll
    for (int mt = 0; mt < 2; mt++) {
        int rb = warp * 32 + mt * 16;
#pragma unroll
        for (int nt = 0; nt < 4; nt++) {
            int col = nt * 8 + 2 * tig;
            psf[(rb + gid    ) * 36 + col    ] = o[mt][nt][0] * inv[mt][0];
            psf[(rb + gid    ) * 36 + col + 1] = o[mt][nt][1] * inv[mt][0];
            psf[(rb + gid + 8) * 36 + col    ] = o[mt][nt][2] * inv[mt][1];
            psf[(rb + gid + 8) * 36 + col + 1] = o[mt][nt][3] * inv[mt][1];
        }
    }
    __syncthreads();

    const size_t head_off = (size_t)bh * DK * TN;
#pragma unroll
    for (int t = 0; t < 8; t++) {
        int idx = tid + t * 128;
        int d = idx >> 5, nv = idx & 31;
        size_t gaddr = head_off + (size_t)d * TN + n0 + nv * 4;
        float4 xv = *(const float4*)(x + gaddr);
        float4 ov;
        ov.x = xv.x + psf[(nv * 4 + 0) * 36 + d];
        ov.y = xv.y + psf[(nv * 4 + 1) * 36 + d];
        ov.z = xv.z + psf[(nv * 4 + 2) * 36 + d];
        ov.w = xv.w + psf[(nv * 4 + 3) * 36 + d];
        *(float4*)(out + gaddr) = ov;
    }
}

// ---------------------------------------------------------------------------
extern "C" void kernel_launch(void* const* d_in, const int* in_sizes, int n_in,
                              void* d_out, int out_size)
{
    const float* x  = (const float*)d_in[0];
    const float* wq = (const float*)d_in[1];
    const float* wk = (const float*)d_in[2];
    const float* wv = (const float*)d_in[3];
    float* out = (float*)d_out;

    uint32_t* qt; cudaGetSymbolAddress((void**)&qt, g_qt);
    uint32_t* kt; cudaGetSymbolAddress((void**)&kt, g_kt);
    uint32_t* vt; cudaGetSymbolAddress((void**)&vt, g_v);
    uint32_t* xf; cudaGetSymbolAddress((void**)&xf, g_xf);
    uint32_t* wf; cudaGetSymbolAddress((void**)&wf, g_wf);

    prep_w_kernel<<<192, 256>>>(wq, wk, wv, wf);
    prep_x_kernel<<<dim3(576, 1, B), 256>>>(x, xf);
    proj_kernel<<<dim3(18, 12, B), 128>>>(xf, wf, qt, kt, vt);
    attn_kernel<<<dim3(TN / 128, NHEADS, B), 128>>>(qt, kt, vt, x, out);
}

// round 9
// speedup vs baseline: 1.2002x; 1.2002x over previous
#include <cuda_runtime.h>
#include <cuda_bf16.h>
#include <cstdint>

// Shapes (fixed by the problem)
#define B 4
#define C 256
#define NHEADS 8
#define DK 32
#define TN 2304            // H*W
#define BH (B * NHEADS)
#define NBLK (TN / 8)      // 288 8-row token blocks
#define SCALE 0.17677669529663687f  // 1/sqrt(32)
#define LOG2E 1.4426950408889634f

// Fragment-ordered bf16 scratch (u32 words):
__device__ uint32_t g_qt[BH * NBLK * 2 * 64];
__device__ uint32_t g_kt[BH * NBLK * 2 * 64];
__device__ uint32_t g_v [BH * 4 * 144 * 64];
__device__ uint32_t g_xf[B * NBLK * 16 * 64];
__device__ uint32_t g_wf[3 * 32 * 16 * 64];

// ---------------------------------------------------------------------------
__device__ __forceinline__ float ex2(float x) {
    float y;
    asm("ex2.approx.f32 %0, %1;" : "=f"(y) : "f"(x));
    return y;
}

__device__ __forceinline__ uint32_t pack_bf16(float lo, float hi) {
    uint32_t r;
    asm("cvt.rn.bf16x2.f32 %0, %1, %2;" : "=r"(r) : "f"(hi), "f"(lo));
    return r;
}

__device__ __forceinline__ void mma_bf16(float c[4],
                                         uint32_t a0, uint32_t a1, uint32_t a2, uint32_t a3,
                                         uint32_t b0, uint32_t b1) {
    asm volatile(
        "mma.sync.aligned.m16n8k16.row.col.f32.bf16.bf16.f32 "
        "{%0,%1,%2,%3}, {%4,%5,%6,%7}, {%8,%9}, {%0,%1,%2,%3};"
        : "+f"(c[0]), "+f"(c[1]), "+f"(c[2]), "+f"(c[3])
        : "r"(a0), "r"(a1), "r"(a2), "r"(a3), "r"(b0), "r"(b1));
}

// ---------------------------------------------------------------------------
// prep_w: W[o][c] fp32 -> g_wf frag blocks (bf16). wq scaled by SCALE*LOG2E.
// ---------------------------------------------------------------------------
__global__ __launch_bounds__(256) void prep_w_kernel(
    const float* __restrict__ wq,
    const float* __restrict__ wk,
    const float* __restrict__ wv,
    uint32_t* __restrict__ wf)
{
    int t = blockIdx.x * 256 + threadIdx.x;      // 0 .. 49151
    int proj = t >> 14;
    int r = t & 16383;
    int lane = r & 31;
    int kc = (r >> 5) & 15;
    int blk = r >> 9;
    int o  = blk * 8 + (lane >> 2);
    int tg = lane & 3;
    int c0 = kc * 16 + tg * 2;

    const float* w = (proj == 0) ? wq : (proj == 1) ? wk : wv;
    float s = (proj == 0) ? (SCALE * LOG2E) : 1.0f;

    float2 lo = *(const float2*)(w + o * C + c0);
    float2 hi = *(const float2*)(w + o * C + c0 + 8);
    uint2 out;
    out.x = pack_bf16(lo.x * s, lo.y * s);
    out.y = pack_bf16(hi.x * s, hi.y * s);
    *(uint2*)(wf + ((size_t)(proj * 32 + blk) * 16 + kc) * 64 + lane * 2) = out;
}

// ---------------------------------------------------------------------------
// prep_x: x[b][c][n] fp32 -> g_xf frag blocks (rows = tokens, k = c).
// ---------------------------------------------------------------------------
__global__ __launch_bounds__(256) void prep_x_kernel(
    const float* __restrict__ x,
    uint32_t* __restrict__ xf)
{
    int b = blockIdx.z;
    int t = blockIdx.x * 256 + threadIdx.x;
    int lane = t & 31;
    int kc = (t >> 5) & 15;
    int blk = t >> 9;
    int n  = blk * 8 + (lane >> 2);
    int tg = lane & 3;
    int c0 = kc * 16 + tg * 2;

    const float* xb = x + (size_t)b * C * TN;
    float a0 = xb[(size_t)(c0    ) * TN + n];
    float a1 = xb[(size_t)(c0 + 1) * TN + n];
    float a2 = xb[(size_t)(c0 + 8) * TN + n];
    float a3 = xb[(size_t)(c0 + 9) * TN + n];
    uint2 out;
    out.x = pack_bf16(a0, a1);
    out.y = pack_bf16(a2, a3);
    *(uint2*)(xf + ((size_t)(b * NBLK + blk) * 16 + kc) * 64 + lane * 2) = out;
}

// ---------------------------------------------------------------------------
// Fused projection GEMM, bf16 HMMA, zero smem. grid (18, 12, B).
// ---------------------------------------------------------------------------
__global__ __launch_bounds__(128) void proj_kernel(
    const uint32_t* __restrict__ xf,
    const uint32_t* __restrict__ wf,
    uint32_t* __restrict__ qt,
    uint32_t* __restrict__ kt,
    uint32_t* __restrict__ vt)
{
    const int tid  = threadIdx.x;
    const int warp = tid >> 5;
    const int lane = tid & 31;
    const int gid  = lane >> 2;
    const int tig  = lane & 3;

    const int b    = blockIdx.z;
    const int proj = blockIdx.y >> 2;
    const int ob   = (blockIdx.y & 3) * 64;
    const int rw   = blockIdx.x * 128 + warp * 32;

    const uint32_t* xb = xf + ((size_t)(b * NBLK + (rw >> 3)) * 16) * 64;
    const uint32_t* wb = wf + ((size_t)(proj * 32 + (ob >> 3)) * 16) * 64;

    float acc[2][8][4];
#pragma unroll
    for (int mt = 0; mt < 2; mt++)
#pragma unroll
        for (int nt = 0; nt < 8; nt++)
#pragma unroll
            for (int r = 0; r < 4; r++) acc[mt][nt][r] = 0.f;

#pragma unroll
    for (int kc = 0; kc < 16; kc++) {
        uint32_t a[2][4];
#pragma unroll
        for (int mt = 0; mt < 2; mt++) {
            const uint32_t* p = xb + ((size_t)(mt * 2) * 16 + kc) * 64 + lane * 2;
            uint2 w0 = *(const uint2*)p;
            uint2 w1 = *(const uint2*)(p + 16 * 64);
            a[mt][0] = w0.x; a[mt][1] = w1.x; a[mt][2] = w0.y; a[mt][3] = w1.y;
        }
#pragma unroll
        for (int nt = 0; nt < 8; nt++) {
            uint2 bv = *(const uint2*)(wb + ((size_t)nt * 16 + kc) * 64 + lane * 2);
#pragma unroll
            for (int mt = 0; mt < 2; mt++)
                mma_bf16(acc[mt][nt], a[mt][0], a[mt][1], a[mt][2], a[mt][3],
                         bv.x, bv.y);
        }
    }

    if (proj < 2) {
        uint32_t* dst = (proj == 0) ? qt : kt;
#pragma unroll
        for (int ntp = 0; ntp < 4; ntp++) {
            int nt0 = 2 * ntp;
            int o   = ob + nt0 * 8 + 2 * tig;
            int h   = o >> 5;
            int bh  = b * NHEADS + h;
            int kcq = (o >> 4) & 1;
            size_t cbase = (size_t)bh * (NBLK * 128) + (size_t)kcq * 64
                         + (gid * 4 + tig) * 2;
#pragma unroll
            for (int mt = 0; mt < 2; mt++) {
                int n = rw + mt * 16 + gid;
                size_t addr = cbase + (size_t)(n >> 3) * 128;
                uint2 wlo, whi;
                wlo.x = pack_bf16(acc[mt][nt0    ][0], acc[mt][nt0    ][1]);
                wlo.y = pack_bf16(acc[mt][nt0 + 1][0], acc[mt][nt0 + 1][1]);
                whi.x = pack_bf16(acc[mt][nt0    ][2], acc[mt][nt0    ][3]);
                whi.y = pack_bf16(acc[mt][nt0 + 1][2], acc[mt][nt0 + 1][3]);
                *(uint2*)(dst + addr)       = wlo;
                *(uint2*)(dst + addr + 128) = whi;
            }
        }
    } else {
        bool even = (gid & 1) == 0;
#pragma unroll
        for (int nt = 0; nt < 8; nt++) {
            int o = ob + nt * 8 + 2 * tig + (even ? 0 : 1);
            int d8 = (o & 31) >> 3;
            int bh = b * NHEADS + (o >> 5);
            size_t base = ((size_t)bh * 4 + d8) * (144 * 64);
#pragma unroll
            for (int mt = 0; mt < 2; mt++) {
                float c0 = acc[mt][nt][0], c1 = acc[mt][nt][1];
                float c2 = acc[mt][nt][2], c3 = acc[mt][nt][3];
                float t0 = __shfl_xor_sync(0xffffffffu, c0, 4);
                float t1 = __shfl_xor_sync(0xffffffffu, c1, 4);
                float t2 = __shfl_xor_sync(0xffffffffu, c2, 4);
                float t3 = __shfl_xor_sync(0xffffffffu, c3, 4);
                int n   = rw + mt * 16 + gid;
                int key = n - (gid & 1);
                uint2 wv;
                if (even) { wv.x = pack_bf16(c0, t0); wv.y = pack_bf16(c2, t2); }
                else      { wv.x = pack_bf16(t1, c1); wv.y = pack_bf16(t3, c3); }
                size_t addr = base + (size_t)(key >> 4) * 64
                            + ((o & 7) * 4 + ((key >> 1) & 3)) * 2;
                *(uint2*)(vt + addr) = wv;
            }
        }
    }
}

// ---------------------------------------------------------------------------
// Flash attention: bf16 HMMA + all-MUFU ex2. Full 16-MMA S phase (max ILP),
// then exp/PV interleaved per key-half so MUFU (exp half 1) overlaps the
// tensor pipe (PV half 0) within a warp.
// ---------------------------------------------------------------------------
__global__ __launch_bounds__(128, 4) void attn_kernel(
    const uint32_t* __restrict__ qt,
    const uint32_t* __restrict__ kt,
    const uint32_t* __restrict__ v,
    const float* __restrict__ x,
    float* __restrict__ out)
{
    const int tid  = threadIdx.x;
    const int warp = tid >> 5;
    const int lane = tid & 31;
    const int gid  = lane >> 2;
    const int tig  = lane & 3;

    const int n0 = blockIdx.x * 128;
    const int bh = blockIdx.z * NHEADS + blockIdx.y;
    const uint32_t* qtb = qt + (size_t)bh * NBLK * 128;
    const uint32_t* ktb = kt + (size_t)bh * NBLK * 128;
    const uint32_t* vb  = v  + (size_t)bh * 4 * 144 * 64;

    uint32_t qa[2][2][4];
    {
        int jq = (n0 >> 3) + warp * 4;
#pragma unroll
        for (int mt = 0; mt < 2; mt++)
#pragma unroll
            for (int kc = 0; kc < 2; kc++) {
                const uint32_t* p = qtb + (size_t)(jq + mt * 2) * 128 + kc * 64 + lane * 2;
                uint2 w0 = *(const uint2*)p;
                uint2 w1 = *(const uint2*)(p + 128);
                qa[mt][kc][0] = w0.x;
                qa[mt][kc][1] = w1.x;
                qa[mt][kc][2] = w0.y;
                qa[mt][kc][3] = w1.y;
            }
    }

    float o[2][4][4];
    float lacc[2][2];
#pragma unroll
    for (int mt = 0; mt < 2; mt++) {
        lacc[mt][0] = 0.f; lacc[mt][1] = 0.f;
#pragma unroll
        for (int nt = 0; nt < 4; nt++)
#pragma unroll
            for (int r = 0; r < 4; r++) o[mt][nt][r] = 0.f;
    }

    for (int j0 = 0; j0 < TN; j0 += 32) {
        uint32_t kf[4][2][2], vf[4][2][2];
        {
            const uint32_t* kp = ktb + (size_t)(j0 >> 3) * 128 + lane * 2;
#pragma unroll
            for (int nt = 0; nt < 4; nt++)
#pragma unroll
                for (int kc = 0; kc < 2; kc++) {
                    uint2 wv = *(const uint2*)(kp + nt * 128 + kc * 64);
                    kf[nt][kc][0] = wv.x; kf[nt][kc][1] = wv.y;
                }
            const uint32_t* vp = vb + (size_t)(j0 >> 4) * 64 + lane * 2;
#pragma unroll
            for (int nt = 0; nt < 4; nt++)
#pragma unroll
                for (int kc = 0; kc < 2; kc++) {
                    uint2 wv = *(const uint2*)(vp + (size_t)nt * 144 * 64 + kc * 64);
                    vf[nt][kc][0] = wv.x; vf[nt][kc][1] = wv.y;
                }
        }

        // ---- S = Q K^T : full 16-MMA phase (max tensor ILP) ----
        float sc[2][4][4];
#pragma unroll
        for (int mt = 0; mt < 2; mt++)
#pragma unroll
            for (int nt = 0; nt < 4; nt++)
#pragma unroll
                for (int r = 0; r < 4; r++) sc[mt][nt][r] = 0.f;

#pragma unroll
        for (int kc = 0; kc < 2; kc++)
#pragma unroll
            for (int nt = 0; nt < 4; nt++)
#pragma unroll
                for (int mt = 0; mt < 2; mt++)
                    mma_bf16(sc[mt][nt], qa[mt][kc][0], qa[mt][kc][1],
                             qa[mt][kc][2], qa[mt][kc][3],
                             kf[nt][kc][0], kf[nt][kc][1]);

        // ---- interleaved exp (MUFU) / PV (tensor) per 16-key half ----
#pragma unroll
        for (int p = 0; p < 2; p++) {
            // exp keys [16p, 16p+16): sc[mt][2p], sc[mt][2p+1]
#pragma unroll
            for (int mt = 0; mt < 2; mt++)
#pragma unroll
                for (int nl = 0; nl < 2; nl++) {
                    int nt = 2 * p + nl;
                    float p0 = ex2(sc[mt][nt][0]);
                    float p1 = ex2(sc[mt][nt][1]);
                    float p2 = ex2(sc[mt][nt][2]);
                    float p3 = ex2(sc[mt][nt][3]);
                    sc[mt][nt][0] = p0; sc[mt][nt][1] = p1;
                    sc[mt][nt][2] = p2; sc[mt][nt][3] = p3;
                    lacc[mt][0] += p0 + p1;
                    lacc[mt][1] += p2 + p3;
                }
            // PV for this half (8 MMAs) — overlaps next half's exp on MUFU
#pragma unroll
            for (int mt = 0; mt < 2; mt++) {
                uint32_t a0 = pack_bf16(sc[mt][2 * p    ][0], sc[mt][2 * p    ][1]);
                uint32_t a1 = pack_bf16(sc[mt][2 * p    ][2], sc[mt][2 * p    ][3]);
                uint32_t a2 = pack_bf16(sc[mt][2 * p + 1][0], sc[mt][2 * p + 1][1]);
                uint32_t a3 = pack_bf16(sc[mt][2 * p + 1][2], sc[mt][2 * p + 1][3]);
#pragma unroll
                for (int nt = 0; nt < 4; nt++)
                    mma_bf16(o[mt][nt], a0, a1, a2, a3,
                             vf[nt][p][0], vf[nt][p][1]);
            }
        }
    }

    float inv[2][2];
#pragma unroll
    for (int mt = 0; mt < 2; mt++)
#pragma unroll
        for (int h = 0; h < 2; h++) {
            float l = lacc[mt][h];
            l += __shfl_xor_sync(0xffffffffu, l, 1);
            l += __shfl_xor_sync(0xffffffffu, l, 2);
            inv[mt][h] = 1.f / l;
        }

    __shared__ float psf[128 * 36];
#pragma unroll
    for (int mt = 0; mt < 2; mt++) {
        int rb = warp * 32 + mt * 16;
#pragma unroll
        for (int nt = 0; nt < 4; nt++) {
            int col = nt * 8 + 2 * tig;
            psf[(rb + gid    ) * 36 + col    ] = o[mt][nt][0] * inv[mt][0];
            psf[(rb + gid    ) * 36 + col + 1] = o[mt][nt][1] * inv[mt][0];
            psf[(rb + gid + 8) * 36 + col    ] = o[mt][nt][2] * inv[mt][1];
            psf[(rb + gid + 8) * 36 + col + 1] = o[mt][nt][3] * inv[mt][1];
        }
    }
    __syncthreads();

    const size_t head_off = (size_t)bh * DK * TN;
#pragma unroll
    for (int t = 0; t < 8; t++) {
        int idx = tid + t * 128;
        int d = idx >> 5, nv = idx & 31;
        size_t gaddr = head_off + (size_t)d * TN + n0 + nv * 4;
        float4 xv = *(const float4*)(x + gaddr);
        float4 ov;
        ov.x = xv.x + psf[(nv * 4 + 0) * 36 + d];
        ov.y = xv.y + psf[(nv * 4 + 1) * 36 + d];
        ov.z = xv.z + psf[(nv * 4 + 2) * 36 + d];
        ov.w = xv.w + psf[(nv * 4 + 3) * 36 + d];
        *(float4*)(out + gaddr) = ov;
    }
}

// ---------------------------------------------------------------------------
extern "C" void kernel_launch(void* const* d_in, const int* in_sizes, int n_in,
                              void* d_out, int out_size)
{
    const float* x  = (const float*)d_in[0];
    const float* wq = (const float*)d_in[1];
    const float* wk = (const float*)d_in[2];
    const float* wv = (const float*)d_in[3];
    float* out = (float*)d_out;

    uint32_t* qt; cudaGetSymbolAddress((void**)&qt, g_qt);
    uint32_t* kt; cudaGetSymbolAddress((void**)&kt, g_kt);
    uint32_t* vt; cudaGetSymbolAddress((void**)&vt, g_v);
    uint32_t* xf; cudaGetSymbolAddress((void**)&xf, g_xf);
    uint32_t* wf; cudaGetSymbolAddress((void**)&wf, g_wf);

    prep_w_kernel<<<192, 256>>>(wq, wk, wv, wf);
    prep_x_kernel<<<dim3(576, 1, B), 256>>>(x, xf);
    proj_kernel<<<dim3(18, 12, B), 128>>>(xf, wf, qt, kt, vt);
    attn_kernel<<<dim3(TN / 128, NHEADS, B), 128>>>(qt, kt, vt, x, out);
}

// round 11
// speedup vs baseline: 1.2830x; 1.0690x over previous
#include <cuda_runtime.h>
#include <cuda_bf16.h>
#include <cstdint>

// Shapes (fixed by the problem)
#define B 4
#define C 256
#define NHEADS 8
#define DK 32
#define TN 2304            // H*W
#define BH (B * NHEADS)
#define NBLK (TN / 8)      // 288 8-row token blocks
#define SCALE 0.17677669529663687f  // 1/sqrt(32)
#define LOG2E 1.4426950408889634f
#define ONES_BF16X2 0x3F803F80u

// Fragment-ordered bf16 scratch (u32 words):
__device__ uint32_t g_qt[BH * NBLK * 2 * 64];
__device__ uint32_t g_kt[BH * NBLK * 2 * 64];
__device__ uint32_t g_v [BH * 4 * 144 * 64];
__device__ uint32_t g_xf[B * NBLK * 16 * 64];
__device__ uint32_t g_wf[3 * 32 * 16 * 64];

// ---------------------------------------------------------------------------
// exp2 of two bf16 values in one MUFU op; output is already a bf16x2 A-frag.
__device__ __forceinline__ uint32_t ex2_bf16x2(uint32_t x) {
    uint32_t y;
    asm("ex2.approx.ftz.bf16x2 %0, %1;" : "=r"(y) : "r"(x));
    return y;
}

__device__ __forceinline__ uint32_t pack_bf16(float lo, float hi) {
    uint32_t r;
    asm("cvt.rn.bf16x2.f32 %0, %1, %2;" : "=r"(r) : "f"(hi), "f"(lo));
    return r;
}

__device__ __forceinline__ void mma_bf16(float c[4],
                                         uint32_t a0, uint32_t a1, uint32_t a2, uint32_t a3,
                                         uint32_t b0, uint32_t b1) {
    asm volatile(
        "mma.sync.aligned.m16n8k16.row.col.f32.bf16.bf16.f32 "
        "{%0,%1,%2,%3}, {%4,%5,%6,%7}, {%8,%9}, {%0,%1,%2,%3};"
        : "+f"(c[0]), "+f"(c[1]), "+f"(c[2]), "+f"(c[3])
        : "r"(a0), "r"(a1), "r"(a2), "r"(a3), "r"(b0), "r"(b1));
}

// ---------------------------------------------------------------------------
// prep_w: W[o][c] fp32 -> g_wf frag blocks (bf16). wq scaled by SCALE*LOG2E.
// ---------------------------------------------------------------------------
__global__ __launch_bounds__(256) void prep_w_kernel(
    const float* __restrict__ wq,
    const float* __restrict__ wk,
    const float* __restrict__ wv,
    uint32_t* __restrict__ wf)
{
    int t = blockIdx.x * 256 + threadIdx.x;      // 0 .. 49151
    int proj = t >> 14;
    int r = t & 16383;
    int lane = r & 31;
    int kc = (r >> 5) & 15;
    int blk = r >> 9;
    int o  = blk * 8 + (lane >> 2);
    int tg = lane & 3;
    int c0 = kc * 16 + tg * 2;

    const float* w = (proj == 0) ? wq : (proj == 1) ? wk : wv;
    float s = (proj == 0) ? (SCALE * LOG2E) : 1.0f;

    float2 lo = *(const float2*)(w + o * C + c0);
    float2 hi = *(const float2*)(w + o * C + c0 + 8);
    uint2 out;
    out.x = pack_bf16(lo.x * s, lo.y * s);
    out.y = pack_bf16(hi.x * s, hi.y * s);
    *(uint2*)(wf + ((size_t)(proj * 32 + blk) * 16 + kc) * 64 + lane * 2) = out;
}

// ---------------------------------------------------------------------------
// prep_x: x[b][c][n] fp32 -> g_xf frag blocks (rows = tokens, k = c).
// ---------------------------------------------------------------------------
__global__ __launch_bounds__(256) void prep_x_kernel(
    const float* __restrict__ x,
    uint32_t* __restrict__ xf)
{
    int b = blockIdx.z;
    int t = blockIdx.x * 256 + threadIdx.x;
    int lane = t & 31;
    int kc = (t >> 5) & 15;
    int blk = t >> 9;
    int n  = blk * 8 + (lane >> 2);
    int tg = lane & 3;
    int c0 = kc * 16 + tg * 2;

    const float* xb = x + (size_t)b * C * TN;
    float a0 = xb[(size_t)(c0    ) * TN + n];
    float a1 = xb[(size_t)(c0 + 1) * TN + n];
    float a2 = xb[(size_t)(c0 + 8) * TN + n];
    float a3 = xb[(size_t)(c0 + 9) * TN + n];
    uint2 out;
    out.x = pack_bf16(a0, a1);
    out.y = pack_bf16(a2, a3);
    *(uint2*)(xf + ((size_t)(b * NBLK + blk) * 16 + kc) * 64 + lane * 2) = out;
}

// ---------------------------------------------------------------------------
// Fused projection GEMM, bf16 HMMA, zero smem. grid (18, 12, B).
// ---------------------------------------------------------------------------
__global__ __launch_bounds__(128) void proj_kernel(
    const uint32_t* __restrict__ xf,
    const uint32_t* __restrict__ wf,
    uint32_t* __restrict__ qt,
    uint32_t* __restrict__ kt,
    uint32_t* __restrict__ vt)
{
    const int tid  = threadIdx.x;
    const int warp = tid >> 5;
    const int lane = tid & 31;
    const int gid  = lane >> 2;
    const int tig  = lane & 3;

    const int b    = blockIdx.z;
    const int proj = blockIdx.y >> 2;
    const int ob   = (blockIdx.y & 3) * 64;
    const int rw   = blockIdx.x * 128 + warp * 32;

    const uint32_t* xb = xf + ((size_t)(b * NBLK + (rw >> 3)) * 16) * 64;
    const uint32_t* wb = wf + ((size_t)(proj * 32 + (ob >> 3)) * 16) * 64;

    float acc[2][8][4];
#pragma unroll
    for (int mt = 0; mt < 2; mt++)
#pragma unroll
        for (int nt = 0; nt < 8; nt++)
#pragma unroll
            for (int r = 0; r < 4; r++) acc[mt][nt][r] = 0.f;

#pragma unroll
    for (int kc = 0; kc < 16; kc++) {
        uint32_t a[2][4];
#pragma unroll
        for (int mt = 0; mt < 2; mt++) {
            const uint32_t* p = xb + ((size_t)(mt * 2) * 16 + kc) * 64 + lane * 2;
            uint2 w0 = *(const uint2*)p;
            uint2 w1 = *(const uint2*)(p + 16 * 64);
            a[mt][0] = w0.x; a[mt][1] = w1.x; a[mt][2] = w0.y; a[mt][3] = w1.y;
        }
#pragma unroll
        for (int nt = 0; nt < 8; nt++) {
            uint2 bv = *(const uint2*)(wb + ((size_t)nt * 16 + kc) * 64 + lane * 2);
#pragma unroll
            for (int mt = 0; mt < 2; mt++)
                mma_bf16(acc[mt][nt], a[mt][0], a[mt][1], a[mt][2], a[mt][3],
                         bv.x, bv.y);
        }
    }

    if (proj < 2) {
        uint32_t* dst = (proj == 0) ? qt : kt;
#pragma unroll
        for (int ntp = 0; ntp < 4; ntp++) {
            int nt0 = 2 * ntp;
            int o   = ob + nt0 * 8 + 2 * tig;
            int h   = o >> 5;
            int bh  = b * NHEADS + h;
            int kcq = (o >> 4) & 1;
            size_t cbase = (size_t)bh * (NBLK * 128) + (size_t)kcq * 64
                         + (gid * 4 + tig) * 2;
#pragma unroll
            for (int mt = 0; mt < 2; mt++) {
                int n = rw + mt * 16 + gid;
                size_t addr = cbase + (size_t)(n >> 3) * 128;
                uint2 wlo, whi;
                wlo.x = pack_bf16(acc[mt][nt0    ][0], acc[mt][nt0    ][1]);
                wlo.y = pack_bf16(acc[mt][nt0 + 1][0], acc[mt][nt0 + 1][1]);
                whi.x = pack_bf16(acc[mt][nt0    ][2], acc[mt][nt0    ][3]);
                whi.y = pack_bf16(acc[mt][nt0 + 1][2], acc[mt][nt0 + 1][3]);
                *(uint2*)(dst + addr)       = wlo;
                *(uint2*)(dst + addr + 128) = whi;
            }
        }
    } else {
        bool even = (gid & 1) == 0;
#pragma unroll
        for (int nt = 0; nt < 8; nt++) {
            int o = ob + nt * 8 + 2 * tig + (even ? 0 : 1);
            int d8 = (o & 31) >> 3;
            int bh = b * NHEADS + (o >> 5);
            size_t base = ((size_t)bh * 4 + d8) * (144 * 64);
#pragma unroll
            for (int mt = 0; mt < 2; mt++) {
                float c0 = acc[mt][nt][0], c1 = acc[mt][nt][1];
                float c2 = acc[mt][nt][2], c3 = acc[mt][nt][3];
                float t0 = __shfl_xor_sync(0xffffffffu, c0, 4);
                float t1 = __shfl_xor_sync(0xffffffffu, c1, 4);
                float t2 = __shfl_xor_sync(0xffffffffu, c2, 4);
                float t3 = __shfl_xor_sync(0xffffffffu, c3, 4);
                int n   = rw + mt * 16 + gid;
                int key = n - (gid & 1);
                uint2 wv;
                if (even) { wv.x = pack_bf16(c0, t0); wv.y = pack_bf16(c2, t2); }
                else      { wv.x = pack_bf16(t1, c1); wv.y = pack_bf16(t3, c3); }
                size_t addr = base + (size_t)(key >> 4) * 64
                            + ((o & 7) * 4 + ((key >> 1) & 3)) * 2;
                *(uint2*)(vt + addr) = wv;
            }
        }
    }
}

// ---------------------------------------------------------------------------
// Flash attention: bf16 HMMA; softmax exp via ex2.approx.ftz.bf16x2 (2 exps
// per MUFU op, output directly in A-fragment format); l via ones-MMA on the
// tensor pipe (fp32 accumulation, no shfl reduction needed).
// ---------------------------------------------------------------------------
__global__ __launch_bounds__(128, 4) void attn_kernel(
    const uint32_t* __restrict__ qt,
    const uint32_t* __restrict__ kt,
    const uint32_t* __restrict__ v,
    const float* __restrict__ x,
    float* __restrict__ out)
{
    const int tid  = threadIdx.x;
    const int warp = tid >> 5;
    const int lane = tid & 31;
    const int gid  = lane >> 2;
    const int tig  = lane & 3;

    const int n0 = blockIdx.x * 128;
    const int bh = blockIdx.z * NHEADS + blockIdx.y;
    const uint32_t* qtb = qt + (size_t)bh * NBLK * 128;
    const uint32_t* ktb = kt + (size_t)bh * NBLK * 128;
    const uint32_t* vb  = v  + (size_t)bh * 4 * 144 * 64;

    uint32_t qa[2][2][4];
    {
        int jq = (n0 >> 3) + warp * 4;
#pragma unroll
        for (int mt = 0; mt < 2; mt++)
#pragma unroll
            for (int kc = 0; kc < 2; kc++) {
                const uint32_t* p = qtb + (size_t)(jq + mt * 2) * 128 + kc * 64 + lane * 2;
                uint2 w0 = *(const uint2*)p;
                uint2 w1 = *(const uint2*)(p + 128);
                qa[mt][kc][0] = w0.x;
                qa[mt][kc][1] = w1.x;
                qa[mt][kc][2] = w0.y;
                qa[mt][kc][3] = w1.y;
            }
    }

    float o[2][4][4];
    float lacc[2][4];   // ones-MMA accumulators: [mt], rows (gid, gid+8) in c0/c2
#pragma unroll
    for (int mt = 0; mt < 2; mt++) {
#pragma unroll
        for (int r = 0; r < 4; r++) lacc[mt][r] = 0.f;
#pragma unroll
        for (int nt = 0; nt < 4; nt++)
#pragma unroll
            for (int r = 0; r < 4; r++) o[mt][nt][r] = 0.f;
    }

    for (int j0 = 0; j0 < TN; j0 += 32) {
        uint32_t kf[4][2][2], vf[4][2][2];
        {
            const uint32_t* kp = ktb + (size_t)(j0 >> 3) * 128 + lane * 2;
#pragma unroll
            for (int nt = 0; nt < 4; nt++)
#pragma unroll
                for (int kc = 0; kc < 2; kc++) {
                    uint2 wv = *(const uint2*)(kp + nt * 128 + kc * 64);
                    kf[nt][kc][0] = wv.x; kf[nt][kc][1] = wv.y;
                }
            const uint32_t* vp = vb + (size_t)(j0 >> 4) * 64 + lane * 2;
#pragma unroll
            for (int nt = 0; nt < 4; nt++)
#pragma unroll
                for (int kc = 0; kc < 2; kc++) {
                    uint2 wv = *(const uint2*)(vp + (size_t)nt * 144 * 64 + kc * 64);
                    vf[nt][kc][0] = wv.x; vf[nt][kc][1] = wv.y;
                }
        }

        // ---- S = Q K^T : full 16-MMA phase ----
        float sc[2][4][4];
#pragma unroll
        for (int mt = 0; mt < 2; mt++)
#pragma unroll
            for (int nt = 0; nt < 4; nt++)
#pragma unroll
                for (int r = 0; r < 4; r++) sc[mt][nt][r] = 0.f;

#pragma unroll
        for (int kc = 0; kc < 2; kc++)
#pragma unroll
            for (int nt = 0; nt < 4; nt++)
#pragma unroll
                for (int mt = 0; mt < 2; mt++)
                    mma_bf16(sc[mt][nt], qa[mt][kc][0], qa[mt][kc][1],
                             qa[mt][kc][2], qa[mt][kc][3],
                             kf[nt][kc][0], kf[nt][kc][1]);

        // ---- pack S pairs to bf16x2, exp both halves in ONE MUFU op each.
        // pa[mt][p][*] is directly the PV A-fragment.
        uint32_t pa[2][2][4];
#pragma unroll
        for (int mt = 0; mt < 2; mt++)
#pragma unroll
            for (int p = 0; p < 2; p++) {
                pa[mt][p][0] = ex2_bf16x2(pack_bf16(sc[mt][2*p  ][0], sc[mt][2*p  ][1]));
                pa[mt][p][1] = ex2_bf16x2(pack_bf16(sc[mt][2*p  ][2], sc[mt][2*p  ][3]));
                pa[mt][p][2] = ex2_bf16x2(pack_bf16(sc[mt][2*p+1][0], sc[mt][2*p+1][1]));
                pa[mt][p][3] = ex2_bf16x2(pack_bf16(sc[mt][2*p+1][2], sc[mt][2*p+1][3]));
            }

        // ---- O += P V ;  l += P @ ones (same fragments, fp32 accum) ----
#pragma unroll
        for (int p = 0; p < 2; p++)
#pragma unroll
            for (int mt = 0; mt < 2; mt++) {
#pragma unroll
                for (int nt = 0; nt < 4; nt++)
                    mma_bf16(o[mt][nt], pa[mt][p][0], pa[mt][p][1],
                             pa[mt][p][2], pa[mt][p][3],
                             vf[nt][p][0], vf[nt][p][1]);
                mma_bf16(lacc[mt], pa[mt][p][0], pa[mt][p][1],
                         pa[mt][p][2], pa[mt][p][3],
                         ONES_BF16X2, ONES_BF16X2);
            }
    }

    // ---- normalize: lacc c0 = row gid sum, c2 = row gid+8 sum (no shfl) ----
    float inv[2][2];
#pragma unroll
    for (int mt = 0; mt < 2; mt++) {
        inv[mt][0] = 1.f / lacc[mt][0];
        inv[mt][1] = 1.f / lacc[mt][2];
    }

    __shared__ float psf[128 * 36];
#pragma unroll
    for (int mt = 0; mt < 2; mt++) {
        int rb = warp * 32 + mt * 16;
#pragma unroll
        for (int nt = 0; nt < 4; nt++) {
            int col = nt * 8 + 2 * tig;
            psf[(rb + gid    ) * 36 + col    ] = o[mt][nt][0] * inv[mt][0];
            psf[(rb + gid    ) * 36 + col + 1] = o[mt][nt][1] * inv[mt][0];
            psf[(rb + gid + 8) * 36 + col    ] = o[mt][nt][2] * inv[mt][1];
            psf[(rb + gid + 8) * 36 + col + 1] = o[mt][nt][3] * inv[mt][1];
        }
    }
    __syncthreads();

    const size_t head_off = (size_t)bh * DK * TN;
#pragma unroll
    for (int t = 0; t < 8; t++) {
        int idx = tid + t * 128;
        int d = idx >> 5, nv = idx & 31;
        size_t gaddr = head_off + (size_t)d * TN + n0 + nv * 4;
        float4 xv = *(const float4*)(x + gaddr);
        float4 ov;
        ov.x = xv.x + psf[(nv * 4 + 0) * 36 + d];
        ov.y = xv.y + psf[(nv * 4 + 1) * 36 + d];
        ov.z = xv.z + psf[(nv * 4 + 2) * 36 + d];
        ov.w = xv.w + psf[(nv * 4 + 3) * 36 + d];
        *(float4*)(out + gaddr) = ov;
    }
}

// ---------------------------------------------------------------------------
extern "C" void kernel_launch(void* const* d_in, const int* in_sizes, int n_in,
                              void* d_out, int out_size)
{
    const float* x  = (const float*)d_in[0];
    const float* wq = (const float*)d_in[1];
    const float* wk = (const float*)d_in[2];
    const float* wv = (const float*)d_in[3];
    float* out = (float*)d_out;

    uint32_t* qt; cudaGetSymbolAddress((void**)&qt, g_qt);
    uint32_t* kt; cudaGetSymbolAddress((void**)&kt, g_kt);
    uint32_t* vt; cudaGetSymbolAddress((void**)&vt, g_v);
    uint32_t* xf; cudaGetSymbolAddress((void**)&xf, g_xf);
    uint32_t* wf; cudaGetSymbolAddress((void**)&wf, g_wf);

    prep_w_kernel<<<192, 256>>>(wq, wk, wv, wf);
    prep_x_kernel<<<dim3(576, 1, B), 256>>>(x, xf);
    proj_kernel<<<dim3(18, 12, B), 128>>>(xf, wf, qt, kt, vt);
    attn_kernel<<<dim3(TN / 128, NHEADS, B), 128>>>(qt, kt, vt, x, out);
}

// round 12
// speedup vs baseline: 1.3368x; 1.0419x over previous
#include <cuda_runtime.h>
#include <cuda_bf16.h>
#include <cstdint>

// Shapes (fixed by the problem)
#define B 4
#define C 256
#define NHEADS 8
#define DK 32
#define TN 2304            // H*W
#define BH (B * NHEADS)
#define NBLK (TN / 8)      // 288 8-row token blocks
#define SCALE 0.17677669529663687f  // 1/sqrt(32)
#define LOG2E 1.4426950408889634f
#define ONES_BF16X2 0x3F803F80u

// Fragment-ordered bf16 scratch (u32 words):
__device__ uint32_t g_qt[BH * NBLK * 2 * 64];
__device__ uint32_t g_kt[BH * NBLK * 2 * 64];
__device__ uint32_t g_v [BH * 4 * 144 * 64];
__device__ uint32_t g_xf[B * NBLK * 16 * 64];
__device__ uint32_t g_wf[3 * 32 * 16 * 64];

// ---------------------------------------------------------------------------
__device__ __forceinline__ uint32_t ex2_bf16x2(uint32_t x) {
    uint32_t y;
    asm("ex2.approx.ftz.bf16x2 %0, %1;" : "=r"(y) : "r"(x));
    return y;
}

__device__ __forceinline__ uint32_t pack_bf16(float lo, float hi) {
    uint32_t r;
    asm("cvt.rn.bf16x2.f32 %0, %1, %2;" : "=r"(r) : "f"(hi), "f"(lo));
    return r;
}

__device__ __forceinline__ void mma_bf16(float c[4],
                                         uint32_t a0, uint32_t a1, uint32_t a2, uint32_t a3,
                                         uint32_t b0, uint32_t b1) {
    asm volatile(
        "mma.sync.aligned.m16n8k16.row.col.f32.bf16.bf16.f32 "
        "{%0,%1,%2,%3}, {%4,%5,%6,%7}, {%8,%9}, {%0,%1,%2,%3};"
        : "+f"(c[0]), "+f"(c[1]), "+f"(c[2]), "+f"(c[3])
        : "r"(a0), "r"(a1), "r"(a2), "r"(a3), "r"(b0), "r"(b1));
}

// ---------------------------------------------------------------------------
// prep_w: W[o][c] fp32 -> g_wf frag blocks (bf16). wq scaled by SCALE*LOG2E.
// ---------------------------------------------------------------------------
__global__ __launch_bounds__(256) void prep_w_kernel(
    const float* __restrict__ wq,
    const float* __restrict__ wk,
    const float* __restrict__ wv,
    uint32_t* __restrict__ wf)
{
    int t = blockIdx.x * 256 + threadIdx.x;      // 0 .. 49151
    int proj = t >> 14;
    int r = t & 16383;
    int lane = r & 31;
    int kc = (r >> 5) & 15;
    int blk = r >> 9;
    int o  = blk * 8 + (lane >> 2);
    int tg = lane & 3;
    int c0 = kc * 16 + tg * 2;

    const float* w = (proj == 0) ? wq : (proj == 1) ? wk : wv;
    float s = (proj == 0) ? (SCALE * LOG2E) : 1.0f;

    float2 lo = *(const float2*)(w + o * C + c0);
    float2 hi = *(const float2*)(w + o * C + c0 + 8);
    uint2 out;
    out.x = pack_bf16(lo.x * s, lo.y * s);
    out.y = pack_bf16(hi.x * s, hi.y * s);
    *(uint2*)(wf + ((size_t)(proj * 32 + blk) * 16 + kc) * 64 + lane * 2) = out;
}

// ---------------------------------------------------------------------------
// prep_x: x[b][c][n] fp32 -> g_xf frag blocks (rows = tokens, k = c).
// ---------------------------------------------------------------------------
__global__ __launch_bounds__(256) void prep_x_kernel(
    const float* __restrict__ x,
    uint32_t* __restrict__ xf)
{
    int b = blockIdx.z;
    int t = blockIdx.x * 256 + threadIdx.x;
    int lane = t & 31;
    int kc = (t >> 5) & 15;
    int blk = t >> 9;
    int n  = blk * 8 + (lane >> 2);
    int tg = lane & 3;
    int c0 = kc * 16 + tg * 2;

    const float* xb = x + (size_t)b * C * TN;
    float a0 = xb[(size_t)(c0    ) * TN + n];
    float a1 = xb[(size_t)(c0 + 1) * TN + n];
    float a2 = xb[(size_t)(c0 + 8) * TN + n];
    float a3 = xb[(size_t)(c0 + 9) * TN + n];
    uint2 out;
    out.x = pack_bf16(a0, a1);
    out.y = pack_bf16(a2, a3);
    *(uint2*)(xf + ((size_t)(b * NBLK + blk) * 16 + kc) * 64 + lane * 2) = out;
}

// ---------------------------------------------------------------------------
// Fused projection GEMM, bf16 HMMA, zero smem. grid (18, 12, B).
// ---------------------------------------------------------------------------
__global__ __launch_bounds__(128) void proj_kernel(
    const uint32_t* __restrict__ xf,
    const uint32_t* __restrict__ wf,
    uint32_t* __restrict__ qt,
    uint32_t* __restrict__ kt,
    uint32_t* __restrict__ vt)
{
    const int tid  = threadIdx.x;
    const int warp = tid >> 5;
    const int lane = tid & 31;
    const int gid  = lane >> 2;
    const int tig  = lane & 3;

    const int b    = blockIdx.z;
    const int proj = blockIdx.y >> 2;
    const int ob   = (blockIdx.y & 3) * 64;
    const int rw   = blockIdx.x * 128 + warp * 32;

    const uint32_t* xb = xf + ((size_t)(b * NBLK + (rw >> 3)) * 16) * 64;
    const uint32_t* wb = wf + ((size_t)(proj * 32 + (ob >> 3)) * 16) * 64;

    float acc[2][8][4];
#pragma unroll
    for (int mt = 0; mt < 2; mt++)
#pragma unroll
        for (int nt = 0; nt < 8; nt++)
#pragma unroll
            for (int r = 0; r < 4; r++) acc[mt][nt][r] = 0.f;

#pragma unroll
    for (int kc = 0; kc < 16; kc++) {
        uint32_t a[2][4];
#pragma unroll
        for (int mt = 0; mt < 2; mt++) {
            const uint32_t* p = xb + ((size_t)(mt * 2) * 16 + kc) * 64 + lane * 2;
            uint2 w0 = *(const uint2*)p;
            uint2 w1 = *(const uint2*)(p + 16 * 64);
            a[mt][0] = w0.x; a[mt][1] = w1.x; a[mt][2] = w0.y; a[mt][3] = w1.y;
        }
#pragma unroll
        for (int nt = 0; nt < 8; nt++) {
            uint2 bv = *(const uint2*)(wb + ((size_t)nt * 16 + kc) * 64 + lane * 2);
#pragma unroll
            for (int mt = 0; mt < 2; mt++)
                mma_bf16(acc[mt][nt], a[mt][0], a[mt][1], a[mt][2], a[mt][3],
                         bv.x, bv.y);
        }
    }

    if (proj < 2) {
        uint32_t* dst = (proj == 0) ? qt : kt;
#pragma unroll
        for (int ntp = 0; ntp < 4; ntp++) {
            int nt0 = 2 * ntp;
            int o   = ob + nt0 * 8 + 2 * tig;
            int h   = o >> 5;
            int bh  = b * NHEADS + h;
            int kcq = (o >> 4) & 1;
            size_t cbase = (size_t)bh * (NBLK * 128) + (size_t)kcq * 64
                         + (gid * 4 + tig) * 2;
#pragma unroll
            for (int mt = 0; mt < 2; mt++) {
                int n = rw + mt * 16 + gid;
                size_t addr = cbase + (size_t)(n >> 3) * 128;
                uint2 wlo, whi;
                wlo.x = pack_bf16(acc[mt][nt0    ][0], acc[mt][nt0    ][1]);
                wlo.y = pack_bf16(acc[mt][nt0 + 1][0], acc[mt][nt0 + 1][1]);
                whi.x = pack_bf16(acc[mt][nt0    ][2], acc[mt][nt0    ][3]);
                whi.y = pack_bf16(acc[mt][nt0 + 1][2], acc[mt][nt0 + 1][3]);
                *(uint2*)(dst + addr)       = wlo;
                *(uint2*)(dst + addr + 128) = whi;
            }
        }
    } else {
        bool even = (gid & 1) == 0;
#pragma unroll
        for (int nt = 0; nt < 8; nt++) {
            int o = ob + nt * 8 + 2 * tig + (even ? 0 : 1);
            int d8 = (o & 31) >> 3;
            int bh = b * NHEADS + (o >> 5);
            size_t base = ((size_t)bh * 4 + d8) * (144 * 64);
#pragma unroll
            for (int mt = 0; mt < 2; mt++) {
                float c0 = acc[mt][nt][0], c1 = acc[mt][nt][1];
                float c2 = acc[mt][nt][2], c3 = acc[mt][nt][3];
                float t0 = __shfl_xor_sync(0xffffffffu, c0, 4);
                float t1 = __shfl_xor_sync(0xffffffffu, c1, 4);
                float t2 = __shfl_xor_sync(0xffffffffu, c2, 4);
                float t3 = __shfl_xor_sync(0xffffffffu, c3, 4);
                int n   = rw + mt * 16 + gid;
                int key = n - (gid & 1);
                uint2 wv;
                if (even) { wv.x = pack_bf16(c0, t0); wv.y = pack_bf16(c2, t2); }
                else      { wv.x = pack_bf16(t1, c1); wv.y = pack_bf16(t3, c3); }
                size_t addr = base + (size_t)(key >> 4) * 64
                            + ((o & 7) * 4 + ((key >> 1) & 3)) * 2;
                *(uint2*)(vt + addr) = wv;
            }
        }
    }
}

// ---------------------------------------------------------------------------
// Flash attention: identical math to R11, but 64-thread CTAs (2 warps,
// 64 queries) -> 9 CTAs/SM = 18 warps/SM instead of 14.4, to fill the
// tensor-pipe gaps left by the per-warp S->exp->PV chain.
// grid = (TN/64, NHEADS, B) = (36, 8, 4).
// ---------------------------------------------------------------------------
__global__ __launch_bounds__(64, 8) void attn_kernel(
    const uint32_t* __restrict__ qt,
    const uint32_t* __restrict__ kt,
    const uint32_t* __restrict__ v,
    const float* __restrict__ x,
    float* __restrict__ out)
{
    const int tid  = threadIdx.x;
    const int warp = tid >> 5;
    const int lane = tid & 31;
    const int gid  = lane >> 2;
    const int tig  = lane & 3;

    const int n0 = blockIdx.x * 64;
    const int bh = blockIdx.z * NHEADS + blockIdx.y;
    const uint32_t* qtb = qt + (size_t)bh * NBLK * 128;
    const uint32_t* ktb = kt + (size_t)bh * NBLK * 128;
    const uint32_t* vb  = v  + (size_t)bh * 4 * 144 * 64;

    uint32_t qa[2][2][4];
    {
        int jq = (n0 >> 3) + warp * 4;
#pragma unroll
        for (int mt = 0; mt < 2; mt++)
#pragma unroll
            for (int kc = 0; kc < 2; kc++) {
                const uint32_t* p = qtb + (size_t)(jq + mt * 2) * 128 + kc * 64 + lane * 2;
                uint2 w0 = *(const uint2*)p;
                uint2 w1 = *(const uint2*)(p + 128);
                qa[mt][kc][0] = w0.x;
                qa[mt][kc][1] = w1.x;
                qa[mt][kc][2] = w0.y;
                qa[mt][kc][3] = w1.y;
            }
    }

    float o[2][4][4];
    float lacc[2][4];   // ones-MMA accumulators
#pragma unroll
    for (int mt = 0; mt < 2; mt++) {
#pragma unroll
        for (int r = 0; r < 4; r++) lacc[mt][r] = 0.f;
#pragma unroll
        for (int nt = 0; nt < 4; nt++)
#pragma unroll
            for (int r = 0; r < 4; r++) o[mt][nt][r] = 0.f;
    }

    for (int j0 = 0; j0 < TN; j0 += 32) {
        uint32_t kf[4][2][2], vf[4][2][2];
        {
            const uint32_t* kp = ktb + (size_t)(j0 >> 3) * 128 + lane * 2;
#pragma unroll
            for (int nt = 0; nt < 4; nt++)
#pragma unroll
                for (int kc = 0; kc < 2; kc++) {
                    uint2 wv = *(const uint2*)(kp + nt * 128 + kc * 64);
                    kf[nt][kc][0] = wv.x; kf[nt][kc][1] = wv.y;
                }
            const uint32_t* vp = vb + (size_t)(j0 >> 4) * 64 + lane * 2;
#pragma unroll
            for (int nt = 0; nt < 4; nt++)
#pragma unroll
                for (int kc = 0; kc < 2; kc++) {
                    uint2 wv = *(const uint2*)(vp + (size_t)nt * 144 * 64 + kc * 64);
                    vf[nt][kc][0] = wv.x; vf[nt][kc][1] = wv.y;
                }
        }

        // ---- S = Q K^T : full 16-MMA phase ----
        float sc[2][4][4];
#pragma unroll
        for (int mt = 0; mt < 2; mt++)
#pragma unroll
            for (int nt = 0; nt < 4; nt++)
#pragma unroll
                for (int r = 0; r < 4; r++) sc[mt][nt][r] = 0.f;

#pragma unroll
        for (int kc = 0; kc < 2; kc++)
#pragma unroll
            for (int nt = 0; nt < 4; nt++)
#pragma unroll
                for (int mt = 0; mt < 2; mt++)
                    mma_bf16(sc[mt][nt], qa[mt][kc][0], qa[mt][kc][1],
                             qa[mt][kc][2], qa[mt][kc][3],
                             kf[nt][kc][0], kf[nt][kc][1]);

        // ---- pack S pairs to bf16x2, exp two at a time on MUFU ----
        uint32_t pa[2][2][4];
#pragma unroll
        for (int mt = 0; mt < 2; mt++)
#pragma unroll
            for (int p = 0; p < 2; p++) {
                pa[mt][p][0] = ex2_bf16x2(pack_bf16(sc[mt][2*p  ][0], sc[mt][2*p  ][1]));
                pa[mt][p][1] = ex2_bf16x2(pack_bf16(sc[mt][2*p  ][2], sc[mt][2*p  ][3]));
                pa[mt][p][2] = ex2_bf16x2(pack_bf16(sc[mt][2*p+1][0], sc[mt][2*p+1][1]));
                pa[mt][p][3] = ex2_bf16x2(pack_bf16(sc[mt][2*p+1][2], sc[mt][2*p+1][3]));
            }

        // ---- O += P V ;  l += P @ ones ----
#pragma unroll
        for (int p = 0; p < 2; p++)
#pragma unroll
            for (int mt = 0; mt < 2; mt++) {
#pragma unroll
                for (int nt = 0; nt < 4; nt++)
                    mma_bf16(o[mt][nt], pa[mt][p][0], pa[mt][p][1],
                             pa[mt][p][2], pa[mt][p][3],
                             vf[nt][p][0], vf[nt][p][1]);
                mma_bf16(lacc[mt], pa[mt][p][0], pa[mt][p][1],
                         pa[mt][p][2], pa[mt][p][3],
                         ONES_BF16X2, ONES_BF16X2);
            }
    }

    // ---- normalize (lacc c0 = row gid sum, c2 = row gid+8 sum) ----
    float inv[2][2];
#pragma unroll
    for (int mt = 0; mt < 2; mt++) {
        inv[mt][0] = 1.f / lacc[mt][0];
        inv[mt][1] = 1.f / lacc[mt][2];
    }

    __shared__ float psf[64 * 36];
#pragma unroll
    for (int mt = 0; mt < 2; mt++) {
        int rb = warp * 32 + mt * 16;
#pragma unroll
        for (int nt = 0; nt < 4; nt++) {
            int col = nt * 8 + 2 * tig;
            psf[(rb + gid    ) * 36 + col    ] = o[mt][nt][0] * inv[mt][0];
            psf[(rb + gid    ) * 36 + col + 1] = o[mt][nt][1] * inv[mt][0];
            psf[(rb + gid + 8) * 36 + col    ] = o[mt][nt][2] * inv[mt][1];
            psf[(rb + gid + 8) * 36 + col + 1] = o[mt][nt][3] * inv[mt][1];
        }
    }
    __syncthreads();

    const size_t head_off = (size_t)bh * DK * TN;
#pragma unroll
    for (int t = 0; t < 8; t++) {
        int idx = tid + t * 64;           // 0..511
        int d = idx >> 4, nv = idx & 15;
        size_t gaddr = head_off + (size_t)d * TN + n0 + nv * 4;
        float4 xv = *(const float4*)(x + gaddr);
        float4 ov;
        ov.x = xv.x + psf[(nv * 4 + 0) * 36 + d];
        ov.y = xv.y + psf[(nv * 4 + 1) * 36 + d];
        ov.z = xv.z + psf[(nv * 4 + 2) * 36 + d];
        ov.w = xv.w + psf[(nv * 4 + 3) * 36 + d];
        *(float4*)(out + gaddr) = ov;
    }
}

// ---------------------------------------------------------------------------
extern "C" void kernel_launch(void* const* d_in, const int* in_sizes, int n_in,
                              void* d_out, int out_size)
{
    const float* x  = (const float*)d_in[0];
    const float* wq = (const float*)d_in[1];
    const float* wk = (const float*)d_in[2];
    const float* wv = (const float*)d_in[3];
    float* out = (float*)d_out;

    uint32_t* qt; cudaGetSymbolAddress((void**)&qt, g_qt);
    uint32_t* kt; cudaGetSymbolAddress((void**)&kt, g_kt);
    uint32_t* vt; cudaGetSymbolAddress((void**)&vt, g_v);
    uint32_t* xf; cudaGetSymbolAddress((void**)&xf, g_xf);
    uint32_t* wf; cudaGetSymbolAddress((void**)&wf, g_wf);

    prep_w_kernel<<<192, 256>>>(wq, wk, wv, wf);
    prep_x_kernel<<<dim3(576, 1, B), 256>>>(x, xf);
    proj_kernel<<<dim3(18, 12, B), 128>>>(xf, wf, qt, kt, vt);
    attn_kernel<<<dim3(TN / 64, NHEADS, B), 64>>>(qt, kt, vt, x, out);
}